// round 4
// baseline (speedup 1.0000x reference)
#include <cuda_runtime.h>
#include <math.h>

#define NPIX 256
#define TPB 352      // 11 warps; 143 blocks => exactly 1 wave on 148 SMs
#define YTILE 32     // rows staged in SMEM per tile (32 KB)

// Scratch for the preprocessed image (softplus + 3x3 Hann conv).
__device__ __align__(16) float d_img[NPIX * NPIX];

// Kernel 1: img = HannConv3x3(softplus(base)), zero-padded SAME.
__global__ void prep_kernel(const float* __restrict__ base) {
    int idx = blockIdx.x * blockDim.x + threadIdx.x;
    if (idx >= NPIX * NPIX) return;
    int px = idx & (NPIX - 1);
    int py = idx >> 8;
    const float w[3] = {0.25f, 0.5f, 0.25f};
    float acc = 0.f;
#pragma unroll
    for (int dy = -1; dy <= 1; ++dy) {
#pragma unroll
        for (int dx = -1; dx <= 1; ++dx) {
            int yy = py + dy, xx = px + dx;
            if (yy >= 0 && yy < NPIX && xx >= 0 && xx < NPIX) {
                float v = base[yy * NPIX + xx];
                float sp = fmaxf(v, 0.f) + log1pf(expf(-fabsf(v)));  // stable softplus
                acc += w[dy + 1] * w[dx + 1] * sp;
            }
        }
    }
    d_img[idx] = acc;
}

// Kernel 2: exact type-2 NUDFT (both axes centered, matching reference math).
// vis[k] = cell^2 * e^{+2pi*i*128*(fu+fv)} * sum_y e^{-2pi*i*fv*y} sum_x img[y,x] e^{-2pi*i*fu*x}
// mode 0: out = float[nvis], real part only (numpy complex->float32 cast drops imag)
// mode 1: out = float2[nvis], interleaved re/im
__global__ void __launch_bounds__(TPB)
vis_kernel(const float* __restrict__ uu,
           const float* __restrict__ vv,
           float* __restrict__ out, int nvis, int mode) {
    __shared__ __align__(16) float srow[YTILE][NPIX];

    const int k = blockIdx.x * TPB + threadIdx.x;
    const float ARCSEC_F = (float)(M_PI / 180.0 / 3600.0);
    const float cell_rad = 0.005f * ARCSEC_F;

    float fu = 0.f, fv = 0.f;
    if (k < nvis) {
        fu = (uu[k] * 1e3f) * cell_rad;   // cycles per pixel in x, |fu| <= 0.25
        fv = (vv[k] * 1e3f) * cell_rad;   // cycles per pixel in y
    }

    // w = exp(-2*pi*i*fu); register twiddle table wt[r] = w^r, r = 0..31.
    float wur, wui; sincospif(-2.f * fu, &wui, &wur);
    float wtr[32], wti[32];
    wtr[0] = 1.f; wti[0] = 0.f;
#pragma unroll
    for (int r = 1; r < 32; ++r) {
        wtr[r] = wtr[r - 1] * wur - wti[r - 1] * wui;
        wti[r] = wtr[r - 1] * wui + wti[r - 1] * wur;
    }
    // W32 = w^32 (exact seed, no drift)
    float W32r, W32i; sincospif(-64.f * fu, &W32i, &W32r);

    // y-phase: b_y = exp(-2*pi*i*fv*y), b_0 = 1.
    float wvr, wvi; sincospif(-2.f * fv, &wvi, &wvr);
    float br = 1.f, bi = 0.f;

    float visr = 0.f, visi = 0.f;

    for (int y0 = 0; y0 < NPIX; y0 += YTILE) {
        __syncthreads();
        const float4* src = (const float4*)(d_img + y0 * NPIX);
        float4* dst = (float4*)&srow[0][0];
        for (int i = threadIdx.x; i < YTILE * NPIX / 4; i += TPB) dst[i] = src[i];
        __syncthreads();

        for (int yy = 0; yy < YTILE; ++yy) {
            const float4* row = (const float4*)srow[yy];
            float rowr = 0.f, rowi = 0.f;
            float Ar = 1.f, Ai = 0.f;            // W32^q
#pragma unroll
            for (int q = 0; q < 8; ++q) {
                float pr = 0.f, pi_ = 0.f;
#pragma unroll
                for (int m = 0; m < 8; ++m) {    // 8 float4 = 32 pixels
                    float4 p = row[q * 8 + m];   // broadcast LDS.128
                    pr  += p.x * wtr[4 * m + 0]; pi_ += p.x * wti[4 * m + 0];
                    pr  += p.y * wtr[4 * m + 1]; pi_ += p.y * wti[4 * m + 1];
                    pr  += p.z * wtr[4 * m + 2]; pi_ += p.z * wti[4 * m + 2];
                    pr  += p.w * wtr[4 * m + 3]; pi_ += p.w * wti[4 * m + 3];
                }
                rowr += pr * Ar - pi_ * Ai;
                rowi += pr * Ai + pi_ * Ar;
                float t = Ar * W32r - Ai * W32i; Ai = Ar * W32i + Ai * W32r; Ar = t;
            }
            visr += rowr * br - rowi * bi;
            visi += rowr * bi + rowi * br;
            float t = br * wvr - bi * wvi; bi = br * wvi + bi * wvr; br = t;
        }
    }

    if (k < nvis) {
        // centering phase: exp(+2*pi*i*128*(fu+fv)) — exact, applied once
        float Sr, Si; sincospif(256.f * fu + 256.f * fv, &Si, &Sr);
        float c2 = cell_rad * cell_rad;
        float orr = (visr * Sr - visi * Si) * c2;
        float oii = (visr * Si + visi * Sr) * c2;
        if (mode == 0) {
            out[k] = orr;                       // real part only
        } else {
            out[2 * k + 0] = orr;               // interleaved complex
            out[2 * k + 1] = oii;
        }
    }
}

extern "C" void kernel_launch(void* const* d_in, const int* in_sizes, int n_in,
                              void* d_out, int out_size) {
    // Robust input mapping: image is uniquely the 65536-element input;
    // the remaining two, in order, are uu then vv.
    int img_i = -1;
    for (int i = 0; i < n_in; ++i)
        if (in_sizes[i] == NPIX * NPIX) { img_i = i; break; }
    if (img_i < 0) img_i = 0;
    int uv_idx[2]; int c = 0;
    for (int i = 0; i < n_in && c < 2; ++i)
        if (i != img_i) uv_idx[c++] = i;

    const float* base = (const float*)d_in[img_i];
    const float* uu   = (const float*)d_in[uv_idx[0]];
    const float* vv   = (const float*)d_in[uv_idx[1]];
    float* out = (float*)d_out;
    const int nvis = in_sizes[uv_idx[0]];

    // Output layout: if the harness buffer holds one float per visibility, the
    // complex64 reference was downcast to float32 (real part). If it holds two
    // per visibility, write interleaved re/im.
    int mode = (out_size >= 2 * nvis) ? 1 : 0;

    prep_kernel<<<(NPIX * NPIX + 255) / 256, 256>>>(base);
    int blocks = (nvis + TPB - 1) / TPB;   // 143 for nvis=50000 -> single wave
    vis_kernel<<<blocks, TPB>>>(uu, vv, out, nvis, mode);
}